// round 7
// baseline (speedup 1.0000x reference)
#include <cuda_runtime.h>
#include <cuda_fp16.h>
#include <cstdint>

#define T_STEPS 8192
#define O_DIM   1024
#define H_DIM   2048
#define A_DIM   512
#define G3H     (3*H_DIM)

// Scan persistent-kernel config: 147 blocks x 14 hidden units, 1 warp per unit.
#define SCAN_NB      147
#define SCAN_UPB     14
#define SCAN_THREADS (SCAN_UPB*32)

// ---------------- scratch (device globals: allocation-free rule) ------------
__device__ float  g_xi[(size_t)T_STEPS * G3H];        // 192 MB: input projections
__device__ float  g_hs[(size_t)T_STEPS * H_DIM];      // 64 MB: hidden states (fp32, GEMMs)
__device__ uint4  g_whh4[(size_t)H_DIM * 3 * 8 * 32]; // 24 MB fp16 W_hh, packed half2 layout

// Per-CTA broadcast record: one 128B L2 line each, double buffered by step parity.
// Layout within record: [0:4) tag (u32, = t+1 when step t's data is ready),
//                       [4:32) 14 fp16 h values for units j = bid*14 .. bid*14+13.
__device__ __align__(128) unsigned char g_rec[2][SCAN_NB][128];

__global__ void reset_tags_kernel() {
    int i = threadIdx.x;                 // 0..293
    if (i < 2*SCAN_NB)
        *reinterpret_cast<unsigned*>(&g_rec[i / SCAN_NB][i % SCAN_NB][0]) = 0u;
}

// ---------------- W_hh fp32 -> fp16 packed relayout --------------------------
// g_whh4[((j*3+g)*8 + c)*32 + l] = half2x4 of W_hh[g*H+j][k], k = c*256 + l*8 + {0..7}
__global__ void convert_whh_kernel(const float* __restrict__ W) {
    int idx = blockIdx.x * blockDim.x + threadIdx.x;      // 0 .. 6144*256-1
    if (idx >= H_DIM * 3 * 8 * 32) return;
    int l  = idx & 31;
    int c  = (idx >> 5) & 7;
    int gj = idx >> 8;            // j*3 + g
    int g  = gj % 3;
    int j  = gj / 3;
    const float* src = W + (size_t)(g*H_DIM + j)*H_DIM + c*256 + l*8;
    float4 v0 = *(const float4*)src;
    float4 v1 = *(const float4*)(src + 4);
    __half2 q0 = __floats2half2_rn(v0.x, v0.y);
    __half2 q1 = __floats2half2_rn(v0.z, v0.w);
    __half2 q2 = __floats2half2_rn(v1.x, v1.y);
    __half2 q3 = __floats2half2_rn(v1.z, v1.w);
    uint4 o;
    o.x = *reinterpret_cast<unsigned*>(&q0);
    o.y = *reinterpret_cast<unsigned*>(&q1);
    o.z = *reinterpret_cast<unsigned*>(&q2);
    o.w = *reinterpret_cast<unsigned*>(&q3);
    g_whh4[idx] = o;
}

// ---------------- generic C = A * B^T + bias (fp32 SIMT, 128x128x16) --------
__global__ __launch_bounds__(256) void gemm_abt_kernel(
    const float* __restrict__ A, const float* __restrict__ B,
    const float* __restrict__ bias, float* __restrict__ C,
    int M, int N, int K)
{
    __shared__ __align__(16) float As[16][132];
    __shared__ __align__(16) float Bs[16][132];
    const int tid = threadIdx.x;
    const int tx = tid & 15, ty = tid >> 4;
    const int m0 = blockIdx.y * 128, n0 = blockIdx.x * 128;

    float acc[8][8];
    #pragma unroll
    for (int i = 0; i < 8; i++)
        #pragma unroll
        for (int j = 0; j < 8; j++) acc[i][j] = 0.0f;

    for (int kt = 0; kt < K; kt += 16) {
        #pragma unroll
        for (int s = 0; s < 2; s++) {
            int f = tid + s*256;
            int row = f >> 2;
            int kq = (f & 3) << 2;
            float4 va = *(const float4*)(A + (size_t)(m0+row)*K + kt + kq);
            As[kq+0][row] = va.x; As[kq+1][row] = va.y;
            As[kq+2][row] = va.z; As[kq+3][row] = va.w;
            float4 vb = *(const float4*)(B + (size_t)(n0+row)*K + kt + kq);
            Bs[kq+0][row] = vb.x; Bs[kq+1][row] = vb.y;
            Bs[kq+2][row] = vb.z; Bs[kq+3][row] = vb.w;
        }
        __syncthreads();
        #pragma unroll
        for (int k = 0; k < 16; k++) {
            float a[8], bb[8];
            *(float4*)(a)    = *(const float4*)&As[k][ty*8];
            *(float4*)(a+4)  = *(const float4*)&As[k][ty*8+4];
            *(float4*)(bb)   = *(const float4*)&Bs[k][tx*8];
            *(float4*)(bb+4) = *(const float4*)&Bs[k][tx*8+4];
            #pragma unroll
            for (int i = 0; i < 8; i++)
                #pragma unroll
                for (int j = 0; j < 8; j++)
                    acc[i][j] = fmaf(a[i], bb[j], acc[i][j]);
        }
        __syncthreads();
    }

    float4 bv0 = *(const float4*)&bias[n0 + tx*8];
    float4 bv1 = *(const float4*)&bias[n0 + tx*8 + 4];
    #pragma unroll
    for (int i = 0; i < 8; i++) {
        float4 o0, o1;
        o0.x = acc[i][0]+bv0.x; o0.y = acc[i][1]+bv0.y;
        o0.z = acc[i][2]+bv0.z; o0.w = acc[i][3]+bv0.w;
        o1.x = acc[i][4]+bv1.x; o1.y = acc[i][5]+bv1.y;
        o1.z = acc[i][6]+bv1.z; o1.w = acc[i][7]+bv1.w;
        float* crow = C + (size_t)(m0 + ty*8 + i)*N + n0 + tx*8;
        *(float4*)(crow)   = o0;
        *(float4*)(crow+4) = o1;
    }
}

// ---------------- scan helpers ----------------------------------------------
__device__ __forceinline__ float sigmoid_f(float x) {
    return 1.0f / (1.0f + __expf(-x));
}
__device__ __forceinline__ float tanh_f(float x) {
    float e = __expf(-2.0f * fabsf(x));
    float t = (1.0f - e) / (1.0f + e);
    return copysignf(t, x);
}
__device__ __forceinline__ __half2 u2h(unsigned u) {
    return *reinterpret_cast<__half2*>(&u);
}
__device__ __forceinline__ void hfma_u4(__half2 acc[4], uint4 w, uint4 h) {
    acc[0] = __hfma2(u2h(w.x), u2h(h.x), acc[0]);
    acc[1] = __hfma2(u2h(w.y), u2h(h.y), acc[1]);
    acc[2] = __hfma2(u2h(w.z), u2h(h.z), acc[2]);
    acc[3] = __hfma2(u2h(w.w), u2h(h.w), acc[3]);
}
__device__ __forceinline__ float acc_to_f32(const __half2 acc[4]) {
    __half2 a = __hadd2(acc[0], acc[1]);
    __half2 b = __hadd2(acc[2], acc[3]);
    float2 fa = __half22float2(a);
    float2 fb = __half22float2(b);
    return (fa.x + fa.y) + (fb.x + fb.y);
}

// ---------------- GRU scan (persistent; distributed tag barrier) ------------
__global__ __launch_bounds__(SCAN_THREADS, 1) void gru_scan_kernel(const float* __restrict__ b_hh)
{
    // h buffer: 2048 fp16 = 4096B, padded to 147*28 = 4116B (record 146 writes
    // 10 tail halves for nonexistent units 2048..2057; never read by the GEMV).
    __shared__ __align__(16) unsigned char smem_h[4128];
    uint4* sh4 = reinterpret_cast<uint4*>(smem_h);

    const int tid  = threadIdx.x;
    const int u    = tid >> 5;
    const int lane = tid & 31;
    const int bid  = blockIdx.x;
    const int j    = bid * SCAN_UPB + u;
    const bool active = (j < H_DIM);

    // Zero h buffer (t=0 uses h = 0).
    for (int i = tid; i < 4128/16; i += SCAN_THREADS) sh4[i] = make_uint4(0,0,0,0);

    // All three gate weight rows -> registers (96 regs/lane).
    uint4 wr[8], wz[8], wn[8];
    #pragma unroll
    for (int c = 0; c < 8; c++) {
        wr[c] = make_uint4(0,0,0,0); wz[c] = wr[c]; wn[c] = wr[c];
    }
    if (active) {
        #pragma unroll
        for (int c = 0; c < 8; c++) {
            wr[c] = g_whh4[((size_t)(j*3 + 0)*8 + c)*32 + lane];
            wz[c] = g_whh4[((size_t)(j*3 + 1)*8 + c)*32 + lane];
            wn[c] = g_whh4[((size_t)(j*3 + 2)*8 + c)*32 + lane];
        }
    }
    float bhr = 0.f, bhz = 0.f, bhn = 0.f;
    if (active) { bhr = b_hh[j]; bhz = b_hh[H_DIM+j]; bhn = b_hh[2*H_DIM+j]; }

    // Consumer assignment: warp u, lane < 11 handles record r = u*11 + lane.
    const int rmine = u*11 + lane;
    const bool rvalid = (lane < 11) && (rmine < SCAN_NB);
    __syncthreads();

    // Prefetch xi for t=0.
    float pxr = 0.f, pxz = 0.f, pxn = 0.f;
    if (active && lane == 0) {
        pxr = g_xi[j]; pxz = g_xi[H_DIM + j]; pxn = g_xi[2*H_DIM + j];
    }
    float hprev = 0.f;

    for (int t = 0; t < T_STEPS; t++) {
        const float xr = pxr, xz = pxz, xn = pxn;
        // Prefetch next step's xi (hidden under this step's GEMV + barrier).
        if (active && lane == 0) {
            int tn = (t + 1 < T_STEPS) ? (t + 1) : t;
            const float* xirow = g_xi + (size_t)tn * G3H;
            pxr = xirow[j]; pxz = xirow[H_DIM+j]; pxn = xirow[2*H_DIM+j];
        }

        // GEMV: 3 gates x 2048, fp16x2. 96 HFMA2 + 8 LDS.128 per lane.
        __half2 ar[4], az[4], an[4];
        #pragma unroll
        for (int i = 0; i < 4; i++) {
            ar[i] = __half2half2(__ushort_as_half(0));
            az[i] = ar[i]; an[i] = ar[i];
        }
        #pragma unroll
        for (int c = 0; c < 8; c++) {
            uint4 hq = sh4[c*32 + lane];
            hfma_u4(ar, wr[c], hq);
            hfma_u4(az, wz[c], hq);
            hfma_u4(an, wn[c], hq);
        }
        float s0 = acc_to_f32(ar), s1 = acc_to_f32(az), s2 = acc_to_f32(an);
        #pragma unroll
        for (int off = 16; off > 0; off >>= 1) {
            s0 += __shfl_xor_sync(0xffffffffu, s0, off);
            s1 += __shfl_xor_sync(0xffffffffu, s1, off);
            s2 += __shfl_xor_sync(0xffffffffu, s2, off);
        }

        const int buf = t & 1;
        if (active && lane == 0) {
            float r = sigmoid_f(xr + s0 + bhr);
            float z = sigmoid_f(xz + s1 + bhz);
            float n = tanh_f(xn + r*(s2 + bhn));
            float hnew = (1.0f - z)*n + z*hprev;
            hprev = hnew;
            g_hs[(size_t)t*H_DIM + j] = hnew;                 // fp32 (output GEMMs)
            // h into this CTA's broadcast record (plain weak store; ordered by
            // the __syncthreads + tid0's release tag store below).
            *reinterpret_cast<__half*>(&g_rec[buf][bid][4 + 2*u]) = __float2half_rn(hnew);
        }

        if (t == T_STEPS - 1) break;   // no successor needs h via the barrier

        // ---- distributed barrier + fused h broadcast ----
        __syncthreads();   // all record h-stores program-ordered before the release
        if (tid == 0)
            asm volatile("st.release.gpu.global.u32 [%0], %1;"
                         :: "l"(&g_rec[buf][bid][0]), "r"((unsigned)(t + 1)) : "memory");
        if (rvalid) {
            const unsigned char* rec = &g_rec[buf][rmine][0];
            const unsigned tgt = (unsigned)(t + 1);
            unsigned cur;
            do {   // acquire: orders + makes the record's data loads below fresh
                asm volatile("ld.acquire.gpu.global.u32 %0, [%1];"
                             : "=r"(cur) : "l"(rec) : "memory");
            } while (cur < tgt);
            uint4 q0 = *reinterpret_cast<const uint4*>(rec);        // tag + h0..h5
            uint4 q1 = *reinterpret_cast<const uint4*>(rec + 16);   // h6..h13
            unsigned* dst = reinterpret_cast<unsigned*>(smem_h + 28*rmine);
            dst[0] = q0.y; dst[1] = q0.z; dst[2] = q0.w;
            dst[3] = q1.x; dst[4] = q1.y; dst[5] = q1.z; dst[6] = q1.w;
        }
        __syncthreads();
    }
}

// ---------------- launch ----------------------------------------------------
extern "C" void kernel_launch(void* const* d_in, const int* in_sizes, int n_in,
                              void* d_out, int out_size)
{
    const float* obs  = (const float*)d_in[0];
    const float* W_ih = (const float*)d_in[1];
    const float* W_hh = (const float*)d_in[2];
    const float* b_ih = (const float*)d_in[3];
    const float* b_hh = (const float*)d_in[4];
    const float* W_o  = (const float*)d_in[5];
    const float* b_o  = (const float*)d_in[6];
    const float* W_d  = (const float*)d_in[7];
    const float* b_d  = (const float*)d_in[8];
    float* out = (float*)d_out;

    float* xi = nullptr; float* hs = nullptr;
    cudaGetSymbolAddress((void**)&xi, g_xi);
    cudaGetSymbolAddress((void**)&hs, g_hs);

    // 0) reset broadcast tags (graph replays reuse device globals)
    reset_tags_kernel<<<1, 2*SCAN_NB>>>();

    // 1) W_hh -> fp16 packed layout
    {
        int total = H_DIM * 3 * 8 * 32;
        convert_whh_kernel<<<(total + 255)/256, 256>>>(W_hh);
    }

    // 2) xi = obs @ W_ih^T + b_ih   [8192 x 6144], K=1024
    gemm_abt_kernel<<<dim3(G3H/128, T_STEPS/128), 256>>>(
        obs, W_ih, b_ih, xi, T_STEPS, G3H, O_DIM);

    // 3) sequential GRU scan (persistent kernel, 8192 internal steps)
    gru_scan_kernel<<<SCAN_NB, SCAN_THREADS>>>(b_hh);

    // 4) o_logits = hs @ W_o^T + b_o ; d_logits = hs @ W_d^T + b_d
    gemm_abt_kernel<<<dim3(A_DIM/128, T_STEPS/128), 256>>>(
        hs, W_o, b_o, out, T_STEPS, A_DIM, H_DIM);
    gemm_abt_kernel<<<dim3(A_DIM/128, T_STEPS/128), 256>>>(
        hs, W_d, b_d, out + (size_t)T_STEPS * A_DIM, T_STEPS, A_DIM, H_DIM);
}

// round 8
// speedup vs baseline: 1.1177x; 1.1177x over previous
#include <cuda_runtime.h>
#include <cuda_fp16.h>
#include <cstdint>

#define T_STEPS 8192
#define O_DIM   1024
#define H_DIM   2048
#define A_DIM   512
#define G3H     (3*H_DIM)

// Scan persistent-kernel config: 147 blocks x 14 hidden units, 1 warp per unit.
#define SCAN_NB      147
#define SCAN_UPB     14
#define SCAN_THREADS (SCAN_UPB*32)

// ---------------- scratch (device globals: allocation-free rule) ------------
__device__ float  g_xi[(size_t)T_STEPS * G3H];        // 192 MB: input projections
__device__ float  g_hs[(size_t)T_STEPS * H_DIM];      // 64 MB: hidden states (fp32, GEMMs)
__device__ uint4  g_whh4[(size_t)H_DIM * 3 * 8 * 32]; // 24 MB fp16 W_hh, packed half2 layout
__device__ __align__(16) __half g_hh[2 * H_DIM];      // double-buffered fp16 h (cross-CTA)
__device__ __align__(128) unsigned g_bar_cnt;          // arrive line (monotonic counter)
__device__ __align__(128) unsigned g_bar_go;           // observe line (monotonic flag)

__global__ void reset_barrier_kernel() { g_bar_cnt = 0u; g_bar_go = 0u; }

// ---------------- W_hh fp32 -> fp16 packed relayout --------------------------
// g_whh4[((j*3+g)*8 + c)*32 + l] = half2x4 of W_hh[g*H+j][k], k = c*256 + l*8 + {0..7}
__global__ void convert_whh_kernel(const float* __restrict__ W) {
    int idx = blockIdx.x * blockDim.x + threadIdx.x;      // 0 .. 6144*256-1
    if (idx >= H_DIM * 3 * 8 * 32) return;
    int l  = idx & 31;
    int c  = (idx >> 5) & 7;
    int gj = idx >> 8;            // j*3 + g
    int g  = gj % 3;
    int j  = gj / 3;
    const float* src = W + (size_t)(g*H_DIM + j)*H_DIM + c*256 + l*8;
    float4 v0 = *(const float4*)src;
    float4 v1 = *(const float4*)(src + 4);
    __half2 q0 = __floats2half2_rn(v0.x, v0.y);
    __half2 q1 = __floats2half2_rn(v0.z, v0.w);
    __half2 q2 = __floats2half2_rn(v1.x, v1.y);
    __half2 q3 = __floats2half2_rn(v1.z, v1.w);
    uint4 o;
    o.x = *reinterpret_cast<unsigned*>(&q0);
    o.y = *reinterpret_cast<unsigned*>(&q1);
    o.z = *reinterpret_cast<unsigned*>(&q2);
    o.w = *reinterpret_cast<unsigned*>(&q3);
    g_whh4[idx] = o;
}

// ---------------- generic C = A * B^T + bias (fp32 SIMT, 128x128x16) --------
__global__ __launch_bounds__(256) void gemm_abt_kernel(
    const float* __restrict__ A, const float* __restrict__ B,
    const float* __restrict__ bias, float* __restrict__ C,
    int M, int N, int K)
{
    __shared__ __align__(16) float As[16][132];
    __shared__ __align__(16) float Bs[16][132];
    const int tid = threadIdx.x;
    const int tx = tid & 15, ty = tid >> 4;
    const int m0 = blockIdx.y * 128, n0 = blockIdx.x * 128;

    float acc[8][8];
    #pragma unroll
    for (int i = 0; i < 8; i++)
        #pragma unroll
        for (int j = 0; j < 8; j++) acc[i][j] = 0.0f;

    for (int kt = 0; kt < K; kt += 16) {
        #pragma unroll
        for (int s = 0; s < 2; s++) {
            int f = tid + s*256;
            int row = f >> 2;
            int kq = (f & 3) << 2;
            float4 va = *(const float4*)(A + (size_t)(m0+row)*K + kt + kq);
            As[kq+0][row] = va.x; As[kq+1][row] = va.y;
            As[kq+2][row] = va.z; As[kq+3][row] = va.w;
            float4 vb = *(const float4*)(B + (size_t)(n0+row)*K + kt + kq);
            Bs[kq+0][row] = vb.x; Bs[kq+1][row] = vb.y;
            Bs[kq+2][row] = vb.z; Bs[kq+3][row] = vb.w;
        }
        __syncthreads();
        #pragma unroll
        for (int k = 0; k < 16; k++) {
            float a[8], bb[8];
            *(float4*)(a)    = *(const float4*)&As[k][ty*8];
            *(float4*)(a+4)  = *(const float4*)&As[k][ty*8+4];
            *(float4*)(bb)   = *(const float4*)&Bs[k][tx*8];
            *(float4*)(bb+4) = *(const float4*)&Bs[k][tx*8+4];
            #pragma unroll
            for (int i = 0; i < 8; i++)
                #pragma unroll
                for (int j = 0; j < 8; j++)
                    acc[i][j] = fmaf(a[i], bb[j], acc[i][j]);
        }
        __syncthreads();
    }

    float4 bv0 = *(const float4*)&bias[n0 + tx*8];
    float4 bv1 = *(const float4*)&bias[n0 + tx*8 + 4];
    #pragma unroll
    for (int i = 0; i < 8; i++) {
        float4 o0, o1;
        o0.x = acc[i][0]+bv0.x; o0.y = acc[i][1]+bv0.y;
        o0.z = acc[i][2]+bv0.z; o0.w = acc[i][3]+bv0.w;
        o1.x = acc[i][4]+bv1.x; o1.y = acc[i][5]+bv1.y;
        o1.z = acc[i][6]+bv1.z; o1.w = acc[i][7]+bv1.w;
        float* crow = C + (size_t)(m0 + ty*8 + i)*N + n0 + tx*8;
        *(float4*)(crow)   = o0;
        *(float4*)(crow+4) = o1;
    }
}

// ---------------- scan helpers ----------------------------------------------
__device__ __forceinline__ float sigmoid_f(float x) {
    return 1.0f / (1.0f + __expf(-x));
}
__device__ __forceinline__ float tanh_f(float x) {
    float e = __expf(-2.0f * fabsf(x));
    float t = (1.0f - e) / (1.0f + e);
    return copysignf(t, x);
}
__device__ __forceinline__ __half2 u2h(unsigned u) {
    return *reinterpret_cast<__half2*>(&u);
}
__device__ __forceinline__ void hfma_u4(__half2 acc[4], uint4 w, uint4 h) {
    acc[0] = __hfma2(u2h(w.x), u2h(h.x), acc[0]);
    acc[1] = __hfma2(u2h(w.y), u2h(h.y), acc[1]);
    acc[2] = __hfma2(u2h(w.z), u2h(h.z), acc[2]);
    acc[3] = __hfma2(u2h(w.w), u2h(h.w), acc[3]);
}
__device__ __forceinline__ float acc_to_f32(const __half2 acc[4]) {
    __half2 a = __hadd2(acc[0], acc[1]);
    __half2 b = __hadd2(acc[2], acc[3]);
    float2 fa = __half22float2(a);
    float2 fb = __half22float2(b);
    return (fa.x + fa.y) + (fb.x + fb.y);
}

// ---------------- GRU scan (persistent; two-phase flag barrier) -------------
__global__ __launch_bounds__(SCAN_THREADS, 1) void gru_scan_kernel(const float* __restrict__ b_hh)
{
    __shared__ __align__(16) uint4 sh4[H_DIM/8];   // h as half2: 256 uint4 = 4 KB

    const int tid  = threadIdx.x;
    const int u    = tid >> 5;
    const int lane = tid & 31;
    const int bid  = blockIdx.x;
    const int j    = bid * SCAN_UPB + u;
    const bool active = (j < H_DIM);

    // Zero h buffer (t=0 uses h = 0).
    for (int i = tid; i < H_DIM/8; i += SCAN_THREADS) sh4[i] = make_uint4(0,0,0,0);

    // All three gate weight rows -> registers (96 regs/lane).
    uint4 wr[8], wz[8], wn[8];
    #pragma unroll
    for (int c = 0; c < 8; c++) {
        wr[c] = make_uint4(0,0,0,0); wz[c] = wr[c]; wn[c] = wr[c];
    }
    if (active) {
        #pragma unroll
        for (int c = 0; c < 8; c++) {
            wr[c] = g_whh4[((size_t)(j*3 + 0)*8 + c)*32 + lane];
            wz[c] = g_whh4[((size_t)(j*3 + 1)*8 + c)*32 + lane];
            wn[c] = g_whh4[((size_t)(j*3 + 2)*8 + c)*32 + lane];
        }
    }
    float bhr = 0.f, bhz = 0.f, bhn = 0.f;
    if (active) { bhr = b_hh[j]; bhz = b_hh[H_DIM+j]; bhn = b_hh[2*H_DIM+j]; }
    __syncthreads();

    // Prefetch xi for t=0.
    float pxr = 0.f, pxz = 0.f, pxn = 0.f;
    if (active && lane == 0) {
        pxr = g_xi[j]; pxz = g_xi[H_DIM + j]; pxn = g_xi[2*H_DIM + j];
    }
    float hprev = 0.f;

    for (int t = 0; t < T_STEPS; t++) {
        const float xr = pxr, xz = pxz, xn = pxn;
        // Prefetch next step's xi (hidden under this step's GEMV + barrier).
        if (active && lane == 0) {
            int tn = (t + 1 < T_STEPS) ? (t + 1) : t;
            const float* xirow = g_xi + (size_t)tn * G3H;
            pxr = xirow[j]; pxz = xirow[H_DIM+j]; pxn = xirow[2*H_DIM+j];
        }

        // GEMV: 3 gates x 2048, fp16x2. 96 HFMA2 + 8 LDS.128 per lane.
        __half2 ar[4], az[4], an[4];
        #pragma unroll
        for (int i = 0; i < 4; i++) {
            ar[i] = __half2half2(__ushort_as_half(0));
            az[i] = ar[i]; an[i] = ar[i];
        }
        #pragma unroll
        for (int c = 0; c < 8; c++) {
            uint4 hq = sh4[c*32 + lane];
            hfma_u4(ar, wr[c], hq);
            hfma_u4(az, wz[c], hq);
            hfma_u4(an, wn[c], hq);
        }
        float s0 = acc_to_f32(ar), s1 = acc_to_f32(az), s2 = acc_to_f32(an);
        #pragma unroll
        for (int off = 16; off > 0; off >>= 1) {
            s0 += __shfl_xor_sync(0xffffffffu, s0, off);
            s1 += __shfl_xor_sync(0xffffffffu, s1, off);
            s2 += __shfl_xor_sync(0xffffffffu, s2, off);
        }

        if (active && lane == 0) {
            float r = sigmoid_f(xr + s0 + bhr);
            float z = sigmoid_f(xz + s1 + bhz);
            float n = tanh_f(xn + r*(s2 + bhn));
            float hnew = (1.0f - z)*n + z*hprev;
            hprev = hnew;
            g_hs[(size_t)t*H_DIM + j] = hnew;                 // fp32 (output GEMMs)
            g_hh[(t & 1)*H_DIM + j] = __float2half_rn(hnew);  // fp16 (cross-CTA broadcast)
        }

        if (t == T_STEPS - 1) break;   // no successor needs h via the barrier

        // ---- two-phase flag barrier + fused h staging (warp 0) ----
        __syncthreads();   // all CTA h stores program-ordered before the arrive
        if (u == 0) {
            const unsigned tgt = (unsigned)(t + 1);
            // Phase 1: arrive on counter line C (write-mostly; only master polls it).
            if (lane == 0)
                asm volatile("red.release.gpu.global.add.u32 [%0], %1;"
                             :: "l"(&g_bar_cnt), "r"(1u) : "memory");
            // Master: detect full arrival on C, then publish go flag G.
            if (bid == 0 && lane == 0) {
                const unsigned ctgt = tgt * (unsigned)SCAN_NB;
                unsigned cur;
                do {
                    asm volatile("ld.acquire.gpu.global.u32 %0, [%1];"
                                 : "=r"(cur) : "l"(&g_bar_cnt) : "memory");
                } while (cur < ctgt);
                asm volatile("st.release.gpu.global.u32 [%0], %1;"
                             :: "l"(&g_bar_go), "r"(tgt) : "memory");
            }
            // Phase 2: everyone observes G (single writer, shared readers; no ping-pong).
            unsigned g;
            do {
                asm volatile("ld.acquire.gpu.global.u32 %0, [%1];"
                             : "=r"(g) : "l"(&g_bar_go) : "memory");
            } while (g < tgt);
            // Stage h_t (4 KB): 8 LDG.128 per lane, MLP=8, then STS.
            const uint4* src = reinterpret_cast<const uint4*>(g_hh) + (t & 1)*256;
            uint4 v[8];
            #pragma unroll
            for (int i = 0; i < 8; i++) v[i] = src[lane + i*32];
            #pragma unroll
            for (int i = 0; i < 8; i++) sh4[lane + i*32] = v[i];
        }
        __syncthreads();
    }
}

// ---------------- launch ----------------------------------------------------
extern "C" void kernel_launch(void* const* d_in, const int* in_sizes, int n_in,
                              void* d_out, int out_size)
{
    const float* obs  = (const float*)d_in[0];
    const float* W_ih = (const float*)d_in[1];
    const float* W_hh = (const float*)d_in[2];
    const float* b_ih = (const float*)d_in[3];
    const float* b_hh = (const float*)d_in[4];
    const float* W_o  = (const float*)d_in[5];
    const float* b_o  = (const float*)d_in[6];
    const float* W_d  = (const float*)d_in[7];
    const float* b_d  = (const float*)d_in[8];
    float* out = (float*)d_out;

    float* xi = nullptr; float* hs = nullptr;
    cudaGetSymbolAddress((void**)&xi, g_xi);
    cudaGetSymbolAddress((void**)&hs, g_hs);

    // 0) reset barrier lines (graph replays reuse device globals)
    reset_barrier_kernel<<<1, 1>>>();

    // 1) W_hh -> fp16 packed layout
    {
        int total = H_DIM * 3 * 8 * 32;
        convert_whh_kernel<<<(total + 255)/256, 256>>>(W_hh);
    }

    // 2) xi = obs @ W_ih^T + b_ih   [8192 x 6144], K=1024
    gemm_abt_kernel<<<dim3(G3H/128, T_STEPS/128), 256>>>(
        obs, W_ih, b_ih, xi, T_STEPS, G3H, O_DIM);

    // 3) sequential GRU scan (persistent kernel, 8192 internal steps)
    gru_scan_kernel<<<SCAN_NB, SCAN_THREADS>>>(b_hh);

    // 4) o_logits = hs @ W_o^T + b_o ; d_logits = hs @ W_d^T + b_d
    gemm_abt_kernel<<<dim3(A_DIM/128, T_STEPS/128), 256>>>(
        hs, W_o, b_o, out, T_STEPS, A_DIM, H_DIM);
    gemm_abt_kernel<<<dim3(A_DIM/128, T_STEPS/128), 256>>>(
        hs, W_d, b_d, out + (size_t)T_STEPS * A_DIM, T_STEPS, A_DIM, H_DIM);
}

// round 9
// speedup vs baseline: 1.6128x; 1.4429x over previous
#include <cuda_runtime.h>
#include <cuda_fp16.h>
#include <cstdint>

#define T_STEPS 8192
#define O_DIM   1024
#define H_DIM   2048
#define A_DIM   512
#define G3H     (3*H_DIM)

// Scan persistent-kernel config: 147 blocks x 14 hidden units, 1 warp per unit.
#define SCAN_NB      147
#define SCAN_UPB     14
#define SCAN_THREADS (SCAN_UPB*32)

// ---------------- scratch (device globals: allocation-free rule) ------------
__device__ float  g_xi[(size_t)T_STEPS * G3H];        // 192 MB: input projections (fp32)
__device__ __half g_hsh[(size_t)T_STEPS * H_DIM];     // 32 MB: fp16 hidden states (broadcast + GEMM A)
__device__ uint4  g_whh4[(size_t)H_DIM * 3 * 8 * 32]; // 24 MB fp16 W_hh, packed half2 layout
__device__ __half g_obs_h[(size_t)T_STEPS * O_DIM];   // 16 MB fp16 obs
__device__ __half g_wih_h[(size_t)G3H * O_DIM];       // 12 MB fp16 W_ih
__device__ __half g_wo_h[(size_t)A_DIM * H_DIM];      // 2 MB fp16 W_o
__device__ __half g_wd_h[(size_t)A_DIM * H_DIM];      // 2 MB fp16 W_d
__device__ __align__(128) unsigned g_bar_cnt;          // monotonic barrier counter

__global__ void reset_barrier_kernel() { g_bar_cnt = 0u; }

// ---------------- generic fp32 -> fp16 convert -------------------------------
__global__ void convert_f2h_kernel(const float* __restrict__ src,
                                   __half* __restrict__ dst, size_t n) {
    size_t i = (size_t)blockIdx.x * blockDim.x + threadIdx.x;
    if (i < n) dst[i] = __float2half_rn(src[i]);
}

// ---------------- W_hh fp32 -> fp16 packed relayout --------------------------
// g_whh4[((j*3+g)*8 + c)*32 + l] = half2x4 of W_hh[g*H+j][k], k = c*256 + l*8 + {0..7}
__global__ void convert_whh_kernel(const float* __restrict__ W) {
    int idx = blockIdx.x * blockDim.x + threadIdx.x;      // 0 .. 6144*256-1
    if (idx >= H_DIM * 3 * 8 * 32) return;
    int l  = idx & 31;
    int c  = (idx >> 5) & 7;
    int gj = idx >> 8;            // j*3 + g
    int g  = gj % 3;
    int j  = gj / 3;
    const float* src = W + (size_t)(g*H_DIM + j)*H_DIM + c*256 + l*8;
    float4 v0 = *(const float4*)src;
    float4 v1 = *(const float4*)(src + 4);
    __half2 q0 = __floats2half2_rn(v0.x, v0.y);
    __half2 q1 = __floats2half2_rn(v0.z, v0.w);
    __half2 q2 = __floats2half2_rn(v1.x, v1.y);
    __half2 q3 = __floats2half2_rn(v1.z, v1.w);
    uint4 o;
    o.x = *reinterpret_cast<unsigned*>(&q0);
    o.y = *reinterpret_cast<unsigned*>(&q1);
    o.z = *reinterpret_cast<unsigned*>(&q2);
    o.w = *reinterpret_cast<unsigned*>(&q3);
    g_whh4[idx] = o;
}

// ---------------- HMMA GEMM: C = A(f16) * B(f16)^T + bias, fp32 accum -------
// A: [M,K] row-major f16, B: [N,K] row-major f16 (= col-major K x N for mma),
// C: [M,N] f32. M%128==0, N%128==0, K%32==0.
__device__ __forceinline__ unsigned sptr(const void* p) {
    return (unsigned)__cvta_generic_to_shared(p);
}

__global__ __launch_bounds__(256) void gemm_hmma_kernel(
    const __half* __restrict__ A, const __half* __restrict__ B,
    const float* __restrict__ bias, float* __restrict__ C,
    int M, int N, int K)
{
    __shared__ __align__(16) __half sA[128*40];   // 128 rows x 32 (pad to 40)
    __shared__ __align__(16) __half sB[128*40];

    const int tid  = threadIdx.x;
    const int wid  = tid >> 5, lane = tid & 31;
    const int wr   = wid & 1;          // warp row: 0/1 -> m-offset 0/64
    const int wc   = wid >> 1;         // warp col: 0..3 -> n-offset 0/32/64/96
    const int m0   = blockIdx.y * 128, n0 = blockIdx.x * 128;

    float acc[4][4][4];
    #pragma unroll
    for (int i = 0; i < 4; i++)
        #pragma unroll
        for (int j = 0; j < 4; j++)
            #pragma unroll
            for (int c = 0; c < 4; c++) acc[i][j][c] = 0.0f;

    for (int kt = 0; kt < K; kt += 32) {
        // Stage tiles: 512 uint4 per operand, 256 threads x 2.
        #pragma unroll
        for (int s = 0; s < 2; s++) {
            int idx = tid + s*256;          // 0..511
            int row = idx >> 2;
            int c8  = (idx & 3) * 8;
            *(uint4*)&sA[row*40 + c8] = *(const uint4*)(A + (size_t)(m0+row)*K + kt + c8);
            *(uint4*)&sB[row*40 + c8] = *(const uint4*)(B + (size_t)(n0+row)*K + kt + c8);
        }
        __syncthreads();

        #pragma unroll
        for (int ks = 0; ks < 2; ks++) {
            unsigned af[4][4], bf[4][2];
            #pragma unroll
            for (int i = 0; i < 4; i++) {
                int row = wr*64 + i*16 + (lane & 15);
                int col = ks*16 + (lane >> 4)*8;
                unsigned a = sptr(&sA[row*40 + col]);
                asm volatile("ldmatrix.sync.aligned.m8n8.x4.shared.b16 {%0,%1,%2,%3}, [%4];"
                             : "=r"(af[i][0]), "=r"(af[i][1]), "=r"(af[i][2]), "=r"(af[i][3])
                             : "r"(a));
            }
            #pragma unroll
            for (int j = 0; j < 4; j++) {
                int row = wc*32 + j*8 + (lane & 7);
                int col = ks*16 + ((lane >> 3) & 1)*8;
                unsigned a = sptr(&sB[row*40 + col]);
                asm volatile("ldmatrix.sync.aligned.m8n8.x2.shared.b16 {%0,%1}, [%2];"
                             : "=r"(bf[j][0]), "=r"(bf[j][1])
                             : "r"(a));
            }
            #pragma unroll
            for (int i = 0; i < 4; i++)
                #pragma unroll
                for (int j = 0; j < 4; j++)
                    asm volatile(
                        "mma.sync.aligned.m16n8k16.row.col.f32.f16.f16.f32 "
                        "{%0,%1,%2,%3}, {%4,%5,%6,%7}, {%8,%9}, {%0,%1,%2,%3};"
                        : "+f"(acc[i][j][0]), "+f"(acc[i][j][1]),
                          "+f"(acc[i][j][2]), "+f"(acc[i][j][3])
                        : "r"(af[i][0]), "r"(af[i][1]), "r"(af[i][2]), "r"(af[i][3]),
                          "r"(bf[j][0]), "r"(bf[j][1]));
        }
        __syncthreads();
    }

    // Epilogue: acc[i][j] -> C rows (wr*64+i*16+g, +8), cols (wc*32+j*8+(lane%4)*2, +1)
    const int gq = lane >> 2, tq = lane & 3;
    #pragma unroll
    for (int i = 0; i < 4; i++) {
        int row = m0 + wr*64 + i*16 + gq;
        #pragma unroll
        for (int j = 0; j < 4; j++) {
            int col = n0 + wc*32 + j*8 + tq*2;
            float b0 = bias[col], b1 = bias[col+1];
            float* p0 = C + (size_t)row*N + col;
            float* p1 = C + (size_t)(row+8)*N + col;
            p0[0] = acc[i][j][0] + b0; p0[1] = acc[i][j][1] + b1;
            p1[0] = acc[i][j][2] + b0; p1[1] = acc[i][j][3] + b1;
        }
    }
}

// ---------------- scan helpers ----------------------------------------------
__device__ __forceinline__ float sigmoid_f(float x) {
    return 1.0f / (1.0f + __expf(-x));
}
__device__ __forceinline__ float tanh_f(float x) {
    float e = __expf(-2.0f * fabsf(x));
    float t = (1.0f - e) / (1.0f + e);
    return copysignf(t, x);
}
__device__ __forceinline__ __half2 u2h(unsigned u) {
    return *reinterpret_cast<__half2*>(&u);
}
__device__ __forceinline__ void hfma_u4(__half2 acc[4], uint4 w, uint4 h) {
    acc[0] = __hfma2(u2h(w.x), u2h(h.x), acc[0]);
    acc[1] = __hfma2(u2h(w.y), u2h(h.y), acc[1]);
    acc[2] = __hfma2(u2h(w.z), u2h(h.z), acc[2]);
    acc[3] = __hfma2(u2h(w.w), u2h(h.w), acc[3]);
}
__device__ __forceinline__ float acc_to_f32(const __half2 acc[4]) {
    __half2 a = __hadd2(acc[0], acc[1]);
    __half2 b = __hadd2(acc[2], acc[3]);
    float2 fa = __half22float2(a);
    float2 fb = __half22float2(b);
    return (fa.x + fa.y) + (fb.x + fb.y);
}

// ---------------- GRU scan (persistent; R5 counter barrier) -----------------
__global__ __launch_bounds__(SCAN_THREADS, 1) void gru_scan_kernel(const float* __restrict__ b_hh)
{
    __shared__ __align__(16) uint4 sh4[H_DIM/8];   // h as half2: 256 uint4 = 4 KB

    const int tid  = threadIdx.x;
    const int u    = tid >> 5;
    const int lane = tid & 31;
    const int j    = blockIdx.x * SCAN_UPB + u;
    const bool active = (j < H_DIM);

    // Zero h buffer (t=0 uses h = 0).
    for (int i = tid; i < H_DIM/8; i += SCAN_THREADS) sh4[i] = make_uint4(0,0,0,0);

    // All three gate weight rows -> registers (96 regs/lane).
    uint4 wr[8], wz[8], wn[8];
    #pragma unroll
    for (int c = 0; c < 8; c++) {
        wr[c] = make_uint4(0,0,0,0); wz[c] = wr[c]; wn[c] = wr[c];
    }
    if (active) {
        #pragma unroll
        for (int c = 0; c < 8; c++) {
            wr[c] = g_whh4[((size_t)(j*3 + 0)*8 + c)*32 + lane];
            wz[c] = g_whh4[((size_t)(j*3 + 1)*8 + c)*32 + lane];
            wn[c] = g_whh4[((size_t)(j*3 + 2)*8 + c)*32 + lane];
        }
    }
    float bhr = 0.f, bhz = 0.f, bhn = 0.f;
    if (active) { bhr = b_hh[j]; bhz = b_hh[H_DIM+j]; bhn = b_hh[2*H_DIM+j]; }
    __syncthreads();

    // Prefetch xi for t=0.
    float pxr = 0.f, pxz = 0.f, pxn = 0.f;
    if (active && lane == 0) {
        pxr = g_xi[j]; pxz = g_xi[H_DIM + j]; pxn = g_xi[2*H_DIM + j];
    }
    float hprev = 0.f;

    for (int t = 0; t < T_STEPS; t++) {
        const float xr = pxr, xz = pxz, xn = pxn;
        // Prefetch next step's xi (hidden under this step's GEMV + barrier).
        if (active && lane == 0) {
            int tn = (t + 1 < T_STEPS) ? (t + 1) : t;
            const float* xirow = g_xi + (size_t)tn * G3H;
            pxr = xirow[j]; pxz = xirow[H_DIM+j]; pxn = xirow[2*H_DIM+j];
        }

        // GEMV: 3 gates x 2048, fp16x2. 96 HFMA2 + 8 LDS.128 per lane.
        __half2 ar[4], az[4], an[4];
        #pragma unroll
        for (int i = 0; i < 4; i++) {
            ar[i] = __half2half2(__ushort_as_half(0));
            az[i] = ar[i]; an[i] = ar[i];
        }
        #pragma unroll
        for (int c = 0; c < 8; c++) {
            uint4 hq = sh4[c*32 + lane];
            hfma_u4(ar, wr[c], hq);
            hfma_u4(az, wz[c], hq);
            hfma_u4(an, wn[c], hq);
        }
        float s0 = acc_to_f32(ar), s1 = acc_to_f32(az), s2 = acc_to_f32(an);
        #pragma unroll
        for (int off = 16; off > 0; off >>= 1) {
            s0 += __shfl_xor_sync(0xffffffffu, s0, off);
            s1 += __shfl_xor_sync(0xffffffffu, s1, off);
            s2 += __shfl_xor_sync(0xffffffffu, s2, off);
        }

        if (active && lane == 0) {
            float r = sigmoid_f(xr + s0 + bhr);
            float z = sigmoid_f(xz + s1 + bhz);
            float n = tanh_f(xn + r*(s2 + bhn));
            float hnew = (1.0f - z)*n + z*hprev;
            hprev = hnew;
            g_hsh[(size_t)t*H_DIM + j] = __float2half_rn(hnew);  // fp16: broadcast + GEMM A
        }

        if (t == T_STEPS - 1) break;   // no successor needs h via the barrier

        // ---- counter barrier + fused h staging (warp 0) — R5 design ----
        __syncthreads();   // all CTA h stores program-ordered before the arrive
        if (u == 0) {
            if (lane == 0)
                asm volatile("red.release.gpu.global.add.u32 [%0], %1;"
                             :: "l"(&g_bar_cnt), "r"(1u) : "memory");
            const unsigned target = (unsigned)(t + 1) * (unsigned)SCAN_NB;
            unsigned cur;
            do {  // acquire load: orders + makes the g_hsh reads below fresh
                asm volatile("ld.acquire.gpu.global.u32 %0, [%1];"
                             : "=r"(cur) : "l"(&g_bar_cnt) : "memory");
            } while (cur < target);
            // Stage h_t (4 KB): 8 LDG.128 per lane, MLP=8, then STS.
            const uint4* src = reinterpret_cast<const uint4*>(g_hsh + (size_t)t*H_DIM);
            uint4 v[8];
            #pragma unroll
            for (int i = 0; i < 8; i++) v[i] = src[lane + i*32];
            #pragma unroll
            for (int i = 0; i < 8; i++) sh4[lane + i*32] = v[i];
        }
        __syncthreads();
    }
}

// ---------------- launch ----------------------------------------------------
extern "C" void kernel_launch(void* const* d_in, const int* in_sizes, int n_in,
                              void* d_out, int out_size)
{
    const float* obs  = (const float*)d_in[0];
    const float* W_ih = (const float*)d_in[1];
    const float* W_hh = (const float*)d_in[2];
    const float* b_ih = (const float*)d_in[3];
    const float* b_hh = (const float*)d_in[4];
    const float* W_o  = (const float*)d_in[5];
    const float* b_o  = (const float*)d_in[6];
    const float* W_d  = (const float*)d_in[7];
    const float* b_d  = (const float*)d_in[8];
    float* out = (float*)d_out;

    float* xi = nullptr; __half* hsh = nullptr;
    __half *obs_h = nullptr, *wih_h = nullptr, *wo_h = nullptr, *wd_h = nullptr;
    cudaGetSymbolAddress((void**)&xi, g_xi);
    cudaGetSymbolAddress((void**)&hsh, g_hsh);
    cudaGetSymbolAddress((void**)&obs_h, g_obs_h);
    cudaGetSymbolAddress((void**)&wih_h, g_wih_h);
    cudaGetSymbolAddress((void**)&wo_h, g_wo_h);
    cudaGetSymbolAddress((void**)&wd_h, g_wd_h);

    // 0) reset barrier counter (graph replays reuse device globals)
    reset_barrier_kernel<<<1, 1>>>();

    // 1) converts: W_hh packed; obs/W_ih/W_o/W_d -> fp16
    {
        int total = H_DIM * 3 * 8 * 32;
        convert_whh_kernel<<<(total + 255)/256, 256>>>(W_hh);
        size_t n;
        n = (size_t)T_STEPS*O_DIM;
        convert_f2h_kernel<<<(int)((n + 255)/256), 256>>>(obs, obs_h, n);
        n = (size_t)G3H*O_DIM;
        convert_f2h_kernel<<<(int)((n + 255)/256), 256>>>(W_ih, wih_h, n);
        n = (size_t)A_DIM*H_DIM;
        convert_f2h_kernel<<<(int)((n + 255)/256), 256>>>(W_o, wo_h, n);
        convert_f2h_kernel<<<(int)((n + 255)/256), 256>>>(W_d, wd_h, n);
    }

    // 2) xi = obs @ W_ih^T + b_ih   [8192 x 6144], K=1024 (tensor cores)
    gemm_hmma_kernel<<<dim3(G3H/128, T_STEPS/128), 256>>>(
        obs_h, wih_h, b_ih, xi, T_STEPS, G3H, O_DIM);

    // 3) sequential GRU scan (persistent kernel, 8192 internal steps)
    gru_scan_kernel<<<SCAN_NB, SCAN_THREADS>>>(b_hh);

    // 4) o_logits = hs @ W_o^T + b_o ; d_logits = hs @ W_d^T + b_d (tensor cores)
    gemm_hmma_kernel<<<dim3(A_DIM/128, T_STEPS/128), 256>>>(
        hsh, wo_h, b_o, out, T_STEPS, A_DIM, H_DIM);
    gemm_hmma_kernel<<<dim3(A_DIM/128, T_STEPS/128), 256>>>(
        hsh, wd_h, b_d, out + (size_t)T_STEPS * A_DIM, T_STEPS, A_DIM, H_DIM);
}